// round 1
// baseline (speedup 1.0000x reference)
#include <cuda_runtime.h>
#include <cstdint>

#define NN 100000
#define NE 1600000
#define LAT 128
#define EF_DIM 32
#define NG 64

// ---------------- device scratch (no allocations allowed) ----------------
__device__ float g_inmsg[NN * LAT];     // pre-activation input message (kept)
__device__ float g_cur[NN * LAT];       // current node embedding
__device__ float g_pool[NN * LAT];      // n2n pooled messages
__device__ float g_pef[NN * EF_DIM];    // pooled edge features per node
__device__ float g_deg[NN];             // in-degree (float) per node for bias
__device__ float g_graph[NG * LAT];     // per-graph accumulator
__device__ float g_WnT[LAT * LAT];      // transposed weights [k][c]
__device__ float g_WcT[LAT * LAT];
__device__ float g_WoT[LAT * LAT];
__device__ float g_WeT[EF_DIM * LAT];

// ---------------- helpers ----------------
__device__ __forceinline__ float lk(float v) { return v > 0.f ? v : 0.01f * v; }

__device__ __forceinline__ void red4(float* p, float4 v) {
    asm volatile("red.global.add.v4.f32 [%0], {%1,%2,%3,%4};"
                 :: "l"(p), "f"(v.x), "f"(v.y), "f"(v.z), "f"(v.w) : "memory");
}

__device__ __forceinline__ void mac4(float4& a, const float4 x,
                                     const float4 w0, const float4 w1,
                                     const float4 w2, const float4 w3) {
    a.x = fmaf(x.x, w0.x, fmaf(x.y, w1.x, fmaf(x.z, w2.x, fmaf(x.w, w3.x, a.x))));
    a.y = fmaf(x.x, w0.y, fmaf(x.y, w1.y, fmaf(x.z, w2.y, fmaf(x.w, w3.y, a.y))));
    a.z = fmaf(x.x, w0.z, fmaf(x.y, w1.z, fmaf(x.z, w2.z, fmaf(x.w, w3.z, a.z))));
    a.w = fmaf(x.x, w0.w, fmaf(x.y, w1.w, fmaf(x.z, w2.w, fmaf(x.w, w3.w, a.w))));
}

// ---------------- weight transpose: Wt[k*C + c] = W[c*K + k] ----------------
__global__ void transpose_k(const float* __restrict__ W, float* __restrict__ Wt,
                            int C, int K) {
    int idx = blockIdx.x * 256 + threadIdx.x;
    if (idx < C * K) {
        int k = idx / C;
        int c = idx % C;
        Wt[k * C + c] = W[c * K + k];
    }
}

// ---------------- generic zero (n4 = count/4) ----------------
__global__ void zero_k(float* __restrict__ p, int n4) {
    int i = blockIdx.x * 256 + threadIdx.x;
    if (i < n4) ((float4*)p)[i] = make_float4(0.f, 0.f, 0.f, 0.f);
}

// ---------------- GEMM: out[r][c] = f( X[r][:128] @ Wt + bias (+ addm) ) ----
// Wt layout: [k][c] (128x128). Block: 256 thr = 8 warps, 64 rows/block.
// warp w handles rows r0..r0+7; lane tx handles cols tx*4..tx*4+3.
template <bool LEAKY, bool ADD, bool POOL>
__global__ void __launch_bounds__(256)
gemm128_k(const float* __restrict__ X, const float* __restrict__ Wt,
          const float* __restrict__ bias, const float* __restrict__ addm,
          const int* __restrict__ gids, float* __restrict__ out, int nrows) {
    __shared__ float sW[64 * LAT];  // one k-half of Wt, 32 KB
    const int tid = threadIdx.x;
    const int w = tid >> 5, tx = tid & 31;
    const int r0 = blockIdx.x * 64 + w * 8;
    const int c0 = tx * 4;

    // clamped row pointers (avoid per-load predication; stores are guarded)
    const float* xp[8];
#pragma unroll
    for (int i = 0; i < 8; i++) {
        int rc = r0 + i;
        if (rc > nrows - 1) rc = nrows - 1;
        xp[i] = X + (size_t)rc * LAT;
    }

    float4 acc[8];
#pragma unroll
    for (int i = 0; i < 8; i++) acc[i] = make_float4(0.f, 0.f, 0.f, 0.f);

#pragma unroll
    for (int kh = 0; kh < 2; kh++) {
        __syncthreads();
        // stage 64x128 slab of Wt (2048 float4, 8 per thread), coalesced
#pragma unroll
        for (int i = 0; i < 8; i++) {
            int idx = tid + i * 256;
            ((float4*)sW)[idx] = ((const float4*)(Wt + kh * 64 * LAT))[idx];
        }
        __syncthreads();

#pragma unroll 4
        for (int kk = 0; kk < 64; kk += 4) {
            float4 wv0 = *(const float4*)&sW[(kk + 0) * LAT + c0];
            float4 wv1 = *(const float4*)&sW[(kk + 1) * LAT + c0];
            float4 wv2 = *(const float4*)&sW[(kk + 2) * LAT + c0];
            float4 wv3 = *(const float4*)&sW[(kk + 3) * LAT + c0];
#pragma unroll
            for (int i = 0; i < 8; i++) {
                float4 xv = *(const float4*)(xp[i] + kh * 64 + kk);
                mac4(acc[i], xv, wv0, wv1, wv2, wv3);
            }
        }
    }

    float4 bv = *(const float4*)&bias[c0];
#pragma unroll
    for (int i = 0; i < 8; i++) {
        int r = r0 + i;
        if (r >= nrows) break;
        float4 o;
        o.x = acc[i].x + bv.x;
        o.y = acc[i].y + bv.y;
        o.z = acc[i].z + bv.z;
        o.w = acc[i].w + bv.w;
        if (ADD) {
            float4 av = *(const float4*)&addm[(size_t)r * LAT + c0];
            o.x += av.x; o.y += av.y; o.z += av.z; o.w += av.w;
        }
        if (LEAKY) { o.x = lk(o.x); o.y = lk(o.y); o.z = lk(o.z); o.w = lk(o.w); }
        if (POOL) {
            int g = __ldg(&gids[r]);
            red4(out + (size_t)g * LAT + c0, o);
        } else {
            *(float4*)&out[(size_t)r * LAT + c0] = o;
        }
    }
}

// ---- K=32 accumulate GEMM: inmsg += pef @ WeT + deg*be; cur = leaky(inmsg) ----
__global__ void __launch_bounds__(256)
gemm32_acc_k(const float* __restrict__ P, const float* __restrict__ WeT,
             const float* __restrict__ be, const float* __restrict__ deg,
             float* __restrict__ inmsg, float* __restrict__ cur, int nrows) {
    __shared__ float sW[EF_DIM * LAT];  // 16 KB
    const int tid = threadIdx.x;
    const int w = tid >> 5, tx = tid & 31;
    const int r0 = blockIdx.x * 64 + w * 8;
    const int c0 = tx * 4;

#pragma unroll
    for (int i = 0; i < 4; i++)
        ((float4*)sW)[tid + i * 256] = ((const float4*)WeT)[tid + i * 256];
    __syncthreads();

    const float* xp[8];
#pragma unroll
    for (int i = 0; i < 8; i++) {
        int rc = r0 + i;
        if (rc > nrows - 1) rc = nrows - 1;
        xp[i] = P + (size_t)rc * EF_DIM;
    }

    float4 acc[8];
#pragma unroll
    for (int i = 0; i < 8; i++) acc[i] = make_float4(0.f, 0.f, 0.f, 0.f);

#pragma unroll
    for (int kk = 0; kk < EF_DIM; kk += 4) {
        float4 wv0 = *(const float4*)&sW[(kk + 0) * LAT + c0];
        float4 wv1 = *(const float4*)&sW[(kk + 1) * LAT + c0];
        float4 wv2 = *(const float4*)&sW[(kk + 2) * LAT + c0];
        float4 wv3 = *(const float4*)&sW[(kk + 3) * LAT + c0];
#pragma unroll
        for (int i = 0; i < 8; i++) {
            float4 xv = *(const float4*)(xp[i] + kk);
            mac4(acc[i], xv, wv0, wv1, wv2, wv3);
        }
    }

    float4 bv = *(const float4*)&be[c0];
#pragma unroll
    for (int i = 0; i < 8; i++) {
        int r = r0 + i;
        if (r >= nrows) break;
        float dg = __ldg(&deg[r]);
        float4 o = *(const float4*)&inmsg[(size_t)r * LAT + c0];
        o.x += acc[i].x + dg * bv.x;
        o.y += acc[i].y + dg * bv.y;
        o.z += acc[i].z + dg * bv.z;
        o.w += acc[i].w + dg * bv.w;
        *(float4*)&inmsg[(size_t)r * LAT + c0] = o;
        float4 c = make_float4(lk(o.x), lk(o.y), lk(o.z), lk(o.w));
        *(float4*)&cur[(size_t)r * LAT + c0] = c;
    }
}

// ---- edge feature pooling: pef[dst] += EF[e]; deg[dst] += 1 ----
__global__ void edge_scatter_k(const float* __restrict__ EF,
                               const int* __restrict__ e2n,
                               float* __restrict__ pef, float* __restrict__ deg,
                               int nedges) {
    long idx = (long)blockIdx.x * 256 + threadIdx.x;
    long total = (long)nedges * 8;
    if (idx < total) {
        int e = (int)(idx >> 3);
        int q = (int)(idx & 7);
        int d = __ldg(&e2n[e]);
        float4 v = *(const float4*)&EF[(size_t)e * EF_DIM + q * 4];
        red4(&pef[(size_t)d * EF_DIM + q * 4], v);
        if (q == 0) atomicAdd(&deg[d], 1.0f);
    }
}

// ---- n2n SpMM: pool[dst] += cur[src], one warp per edge ----
__global__ void __launch_bounds__(256)
spmm_k(const float* __restrict__ cur, const int* __restrict__ src,
       const int* __restrict__ dst, float* __restrict__ pool, int nedges) {
    int gw = (int)(((long)blockIdx.x * 256 + threadIdx.x) >> 5);
    int tx = threadIdx.x & 31;
    if (gw < nedges) {
        int s = __ldg(&src[gw]);
        int d = __ldg(&dst[gw]);
        float4 v = *(const float4*)&cur[(size_t)s * LAT + tx * 4];
        red4(&pool[(size_t)d * LAT + tx * 4], v);
    }
}

// ---- final: out = leaky(graph accumulator) ----
__global__ void final_k(const float* __restrict__ g, float* __restrict__ out) {
    int i = blockIdx.x * 256 + threadIdx.x;
    if (i < NG * LAT) out[i] = lk(g[i]);
}

// ---------------- launch ----------------
extern "C" void kernel_launch(void* const* d_in, const int* in_sizes, int n_in,
                              void* d_out, int out_size) {
    const float* node_feats = (const float*)d_in[0];
    const float* edge_feats = (const float*)d_in[1];
    const int* edge_src = (const int*)d_in[2];
    const int* edge_dst = (const int*)d_in[3];
    const int* e2n_dst = (const int*)d_in[4];
    const int* graph_ids = (const int*)d_in[5];
    const float* wn = (const float*)d_in[6];
    const float* bn = (const float*)d_in[7];
    const float* we = (const float*)d_in[8];
    const float* be = (const float*)d_in[9];
    const float* wc = (const float*)d_in[10];
    const float* bc = (const float*)d_in[11];
    const float* wo = (const float*)d_in[12];
    const float* bo = (const float*)d_in[13];

    int nn = in_sizes[0] / LAT;     // node count (NODE_F==LAT==128)
    int ne = in_sizes[1] / EF_DIM;  // edge count

    float *inmsg, *cur, *pool, *pef, *deg, *graph, *wnT, *wcT, *woT, *weT;
    cudaGetSymbolAddress((void**)&inmsg, g_inmsg);
    cudaGetSymbolAddress((void**)&cur, g_cur);
    cudaGetSymbolAddress((void**)&pool, g_pool);
    cudaGetSymbolAddress((void**)&pef, g_pef);
    cudaGetSymbolAddress((void**)&deg, g_deg);
    cudaGetSymbolAddress((void**)&graph, g_graph);
    cudaGetSymbolAddress((void**)&wnT, g_WnT);
    cudaGetSymbolAddress((void**)&wcT, g_WcT);
    cudaGetSymbolAddress((void**)&woT, g_WoT);
    cudaGetSymbolAddress((void**)&weT, g_WeT);

    const int rowBlocks = (nn + 63) / 64;

    // weight transposes (tiny)
    transpose_k<<<64, 256>>>(wn, wnT, LAT, LAT);
    transpose_k<<<64, 256>>>(wc, wcT, LAT, LAT);
    transpose_k<<<64, 256>>>(wo, woT, LAT, LAT);
    transpose_k<<<16, 256>>>(we, weT, LAT, EF_DIM);

    // zero pooled-edge scratch, degree, graph accumulator
    zero_k<<<(nn * EF_DIM / 4 + 255) / 256, 256>>>(pef, nn * EF_DIM / 4);
    zero_k<<<(nn / 4 + 255) / 256, 256>>>(deg, nn / 4);
    zero_k<<<(NG * LAT / 4 + 255) / 256, 256>>>(graph, NG * LAT / 4);

    // input message: node linear (writes inmsg)
    gemm128_k<false, false, false><<<rowBlocks, 256>>>(
        node_feats, wnT, bn, nullptr, nullptr, inmsg, nn);

    // pooled edge features + degree
    {
        long total = (long)ne * 8;
        int grid = (int)((total + 255) / 256);
        edge_scatter_k<<<grid, 256>>>(edge_feats, e2n_dst, pef, deg, ne);
    }

    // inmsg += pef @ WeT + deg*be ; cur = leaky(inmsg)
    gemm32_acc_k<<<rowBlocks, 256>>>(pef, weT, be, deg, inmsg, cur, nn);

    // 3 rounds of message passing
    for (int lv = 0; lv < 3; lv++) {
        zero_k<<<(nn * LAT / 4 + 255) / 256, 256>>>(pool, nn * LAT / 4);
        {
            long total = (long)ne * 32;
            int grid = (int)((total + 255) / 256);
            spmm_k<<<grid, 256>>>(cur, edge_src, edge_dst, pool, ne);
        }
        gemm128_k<true, true, false><<<rowBlocks, 256>>>(
            pool, wcT, bc, inmsg, nullptr, cur, nn);
    }

    // output linear + leaky + per-graph pooling (atomic)
    gemm128_k<true, false, true><<<rowBlocks, 256>>>(
        cur, woT, bo, nullptr, graph_ids, graph, nn);

    // final leaky to output
    final_k<<<(NG * LAT + 255) / 256, 256>>>(graph, (float*)d_out);
}

// round 2
// speedup vs baseline: 1.3775x; 1.3775x over previous
#include <cuda_runtime.h>
#include <cstdint>

#define NN 100000
#define NE 1600000
#define LAT 128
#define EF_DIM 32
#define NG 64

// ---------------- device scratch (no allocations allowed) ----------------
__device__ float g_inmsg[NN * LAT];     // pre-activation input message (kept)
__device__ float g_cur[NN * LAT];       // current node embedding
__device__ float g_pool[NN * LAT];      // n2n pooled messages
__device__ float g_pef[NN * EF_DIM];    // pooled edge features per node
__device__ float g_deg[NN];             // e2n in-degree (float) for bias
__device__ float g_graph[NG * LAT];     // per-graph accumulator
__device__ float g_WnT[LAT * LAT];      // transposed weights [k][c]
__device__ float g_WcT[LAT * LAT];
__device__ float g_WoT[LAT * LAT];
__device__ float g_WeT[EF_DIM * LAT];
// CSR for n2n (edges sorted by dst)
__device__ int g_ndeg[NN];              // n2n in-degree
__device__ int g_incl[NN];              // scan scratch
__device__ int g_bsum[128];             // block sums for scan
__device__ int g_rowptr[NN + 1];
__device__ int g_woff[NN];              // working offsets for CSR fill
__device__ int g_csrc[NE];              // src node per CSR slot

// ---------------- helpers ----------------
__device__ __forceinline__ float lk(float v) { return v > 0.f ? v : 0.01f * v; }

__device__ __forceinline__ void red4(float* p, float4 v) {
    asm volatile("red.global.add.v4.f32 [%0], {%1,%2,%3,%4};"
                 :: "l"(p), "f"(v.x), "f"(v.y), "f"(v.z), "f"(v.w) : "memory");
}

__device__ __forceinline__ void mac4(float4& a, const float4 x,
                                     const float4 w0, const float4 w1,
                                     const float4 w2, const float4 w3) {
    a.x = fmaf(x.x, w0.x, fmaf(x.y, w1.x, fmaf(x.z, w2.x, fmaf(x.w, w3.x, a.x))));
    a.y = fmaf(x.x, w0.y, fmaf(x.y, w1.y, fmaf(x.z, w2.y, fmaf(x.w, w3.y, a.y))));
    a.z = fmaf(x.x, w0.z, fmaf(x.y, w1.z, fmaf(x.z, w2.z, fmaf(x.w, w3.z, a.z))));
    a.w = fmaf(x.x, w0.w, fmaf(x.y, w1.w, fmaf(x.z, w2.w, fmaf(x.w, w3.w, a.w))));
}

// ---------------- weight transpose: Wt[k*C + c] = W[c*K + k] ----------------
__global__ void transpose_k(const float* __restrict__ W, float* __restrict__ Wt,
                            int C, int K) {
    int idx = blockIdx.x * 256 + threadIdx.x;
    if (idx < C * K) {
        int k = idx / C;
        int c = idx % C;
        Wt[k * C + c] = W[c * K + k];
    }
}

// ---------------- generic zero ----------------
__global__ void zero_k(float* __restrict__ p, int n4) {
    int i = blockIdx.x * 256 + threadIdx.x;
    if (i < n4) ((float4*)p)[i] = make_float4(0.f, 0.f, 0.f, 0.f);
}
__global__ void zeroi_k(int* __restrict__ p, int n) {
    int i = blockIdx.x * 256 + threadIdx.x;
    if (i < n) p[i] = 0;
}

// ---------------- CSR build ----------------
__global__ void count_deg_k(const int* __restrict__ dst, int* __restrict__ ndeg,
                            int nedges) {
    int e = blockIdx.x * 256 + threadIdx.x;
    if (e < nedges) atomicAdd(&ndeg[__ldg(&dst[e])], 1);
}

// inclusive scan per 1024-block
__global__ void __launch_bounds__(1024)
scan1_k(const int* __restrict__ deg, int* __restrict__ incl,
        int* __restrict__ bsum, int n) {
    __shared__ int s[1024];
    int i = blockIdx.x * 1024 + threadIdx.x;
    int v = (i < n) ? deg[i] : 0;
    s[threadIdx.x] = v;
    __syncthreads();
#pragma unroll
    for (int off = 1; off < 1024; off <<= 1) {
        int t = (threadIdx.x >= off) ? s[threadIdx.x - off] : 0;
        __syncthreads();
        s[threadIdx.x] += t;
        __syncthreads();
    }
    if (i < n) incl[i] = s[threadIdx.x];
    if (threadIdx.x == 1023) bsum[blockIdx.x] = s[1023];
}

__global__ void scan2_k(int* __restrict__ bsum, int nb) {
    if (threadIdx.x == 0 && blockIdx.x == 0) {
        int acc = 0;
        for (int b = 0; b < nb; b++) { int v = bsum[b]; bsum[b] = acc; acc += v; }
    }
}

__global__ void scan3_k(const int* __restrict__ incl, const int* __restrict__ bsum,
                        const int* __restrict__ deg, int* __restrict__ rowptr,
                        int* __restrict__ woff, int n, int nedges) {
    int i = blockIdx.x * 256 + threadIdx.x;
    if (i < n) {
        int excl = incl[i] + bsum[i >> 10] - deg[i];
        rowptr[i] = excl;
        woff[i] = excl;
    }
    if (i == 0) rowptr[n] = nedges;
}

__global__ void csr_fill_k(const int* __restrict__ src, const int* __restrict__ dst,
                           int* __restrict__ woff, int* __restrict__ csrc,
                           int nedges) {
    int e = blockIdx.x * 256 + threadIdx.x;
    if (e < nedges) {
        int d = __ldg(&dst[e]);
        int pos = atomicAdd(&woff[d], 1);
        csrc[pos] = __ldg(&src[e]);
    }
}

// ---------------- GEMM: out[r][c] = f( X[r][:128] @ Wt + bias (+ addm) ) ----
template <bool LEAKY, bool ADD, bool POOL>
__global__ void __launch_bounds__(256)
gemm128_k(const float* __restrict__ X, const float* __restrict__ Wt,
          const float* __restrict__ bias, const float* __restrict__ addm,
          const int* __restrict__ gids, float* __restrict__ out, int nrows) {
    __shared__ float sW[64 * LAT];  // one k-half of Wt, 32 KB
    const int tid = threadIdx.x;
    const int w = tid >> 5, tx = tid & 31;
    const int r0 = blockIdx.x * 64 + w * 8;
    const int c0 = tx * 4;

    const float* xp[8];
#pragma unroll
    for (int i = 0; i < 8; i++) {
        int rc = r0 + i;
        if (rc > nrows - 1) rc = nrows - 1;
        xp[i] = X + (size_t)rc * LAT;
    }

    float4 acc[8];
#pragma unroll
    for (int i = 0; i < 8; i++) acc[i] = make_float4(0.f, 0.f, 0.f, 0.f);

#pragma unroll
    for (int kh = 0; kh < 2; kh++) {
        __syncthreads();
#pragma unroll
        for (int i = 0; i < 8; i++) {
            int idx = tid + i * 256;
            ((float4*)sW)[idx] = ((const float4*)(Wt + kh * 64 * LAT))[idx];
        }
        __syncthreads();

#pragma unroll 4
        for (int kk = 0; kk < 64; kk += 4) {
            float4 wv0 = *(const float4*)&sW[(kk + 0) * LAT + c0];
            float4 wv1 = *(const float4*)&sW[(kk + 1) * LAT + c0];
            float4 wv2 = *(const float4*)&sW[(kk + 2) * LAT + c0];
            float4 wv3 = *(const float4*)&sW[(kk + 3) * LAT + c0];
#pragma unroll
            for (int i = 0; i < 8; i++) {
                float4 xv = *(const float4*)(xp[i] + kh * 64 + kk);
                mac4(acc[i], xv, wv0, wv1, wv2, wv3);
            }
        }
    }

    float4 bv = *(const float4*)&bias[c0];
#pragma unroll
    for (int i = 0; i < 8; i++) {
        int r = r0 + i;
        if (r >= nrows) break;
        float4 o;
        o.x = acc[i].x + bv.x;
        o.y = acc[i].y + bv.y;
        o.z = acc[i].z + bv.z;
        o.w = acc[i].w + bv.w;
        if (ADD) {
            float4 av = *(const float4*)&addm[(size_t)r * LAT + c0];
            o.x += av.x; o.y += av.y; o.z += av.z; o.w += av.w;
        }
        if (LEAKY) { o.x = lk(o.x); o.y = lk(o.y); o.z = lk(o.z); o.w = lk(o.w); }
        if (POOL) {
            int g = __ldg(&gids[r]);
            red4(out + (size_t)g * LAT + c0, o);
        } else {
            *(float4*)&out[(size_t)r * LAT + c0] = o;
        }
    }
}

// ---- K=32 accumulate GEMM: inmsg += pef @ WeT + deg*be; cur = leaky(inmsg) ----
__global__ void __launch_bounds__(256)
gemm32_acc_k(const float* __restrict__ P, const float* __restrict__ WeT,
             const float* __restrict__ be, const float* __restrict__ deg,
             float* __restrict__ inmsg, float* __restrict__ cur, int nrows) {
    __shared__ float sW[EF_DIM * LAT];  // 16 KB
    const int tid = threadIdx.x;
    const int w = tid >> 5, tx = tid & 31;
    const int r0 = blockIdx.x * 64 + w * 8;
    const int c0 = tx * 4;

#pragma unroll
    for (int i = 0; i < 4; i++)
        ((float4*)sW)[tid + i * 256] = ((const float4*)WeT)[tid + i * 256];
    __syncthreads();

    const float* xp[8];
#pragma unroll
    for (int i = 0; i < 8; i++) {
        int rc = r0 + i;
        if (rc > nrows - 1) rc = nrows - 1;
        xp[i] = P + (size_t)rc * EF_DIM;
    }

    float4 acc[8];
#pragma unroll
    for (int i = 0; i < 8; i++) acc[i] = make_float4(0.f, 0.f, 0.f, 0.f);

#pragma unroll
    for (int kk = 0; kk < EF_DIM; kk += 4) {
        float4 wv0 = *(const float4*)&sW[(kk + 0) * LAT + c0];
        float4 wv1 = *(const float4*)&sW[(kk + 1) * LAT + c0];
        float4 wv2 = *(const float4*)&sW[(kk + 2) * LAT + c0];
        float4 wv3 = *(const float4*)&sW[(kk + 3) * LAT + c0];
#pragma unroll
        for (int i = 0; i < 8; i++) {
            float4 xv = *(const float4*)(xp[i] + kk);
            mac4(acc[i], xv, wv0, wv1, wv2, wv3);
        }
    }

    float4 bv = *(const float4*)&be[c0];
#pragma unroll
    for (int i = 0; i < 8; i++) {
        int r = r0 + i;
        if (r >= nrows) break;
        float dg = __ldg(&deg[r]);
        float4 o = *(const float4*)&inmsg[(size_t)r * LAT + c0];
        o.x += acc[i].x + dg * bv.x;
        o.y += acc[i].y + dg * bv.y;
        o.z += acc[i].z + dg * bv.z;
        o.w += acc[i].w + dg * bv.w;
        *(float4*)&inmsg[(size_t)r * LAT + c0] = o;
        float4 c = make_float4(lk(o.x), lk(o.y), lk(o.z), lk(o.w));
        *(float4*)&cur[(size_t)r * LAT + c0] = c;
    }
}

// ---- edge feature pooling: pef[dst] += EF[e]; deg[dst] += 1 ----
__global__ void edge_scatter_k(const float* __restrict__ EF,
                               const int* __restrict__ e2n,
                               float* __restrict__ pef, float* __restrict__ deg,
                               int nedges) {
    long idx = (long)blockIdx.x * 256 + threadIdx.x;
    long total = (long)nedges * 8;
    if (idx < total) {
        int e = (int)(idx >> 3);
        int q = (int)(idx & 7);
        int d = __ldg(&e2n[e]);
        float4 v = *(const float4*)&EF[(size_t)e * EF_DIM + q * 4];
        red4(&pef[(size_t)d * EF_DIM + q * 4], v);
        if (q == 0) atomicAdd(&deg[d], 1.0f);
    }
}

// ---- n2n SpMM via CSR gather: pool[node] = sum over csrc rows of cur ----
__global__ void __launch_bounds__(256)
spmm_gather_k(const float* __restrict__ cur, const int* __restrict__ rowptr,
              const int* __restrict__ csrc, float* __restrict__ pool, int nn) {
    int node = (int)(((long)blockIdx.x * 256 + threadIdx.x) >> 5);
    int lane = threadIdx.x & 31;
    if (node >= nn) return;
    int beg = __ldg(&rowptr[node]);
    int end = __ldg(&rowptr[node + 1]);
    float4 acc = make_float4(0.f, 0.f, 0.f, 0.f);
    int j = beg;
    // 4-way unroll for MLP
    for (; j + 3 < end; j += 4) {
        int s0 = __ldg(&csrc[j + 0]);
        int s1 = __ldg(&csrc[j + 1]);
        int s2 = __ldg(&csrc[j + 2]);
        int s3 = __ldg(&csrc[j + 3]);
        float4 a = *(const float4*)&cur[(size_t)s0 * LAT + lane * 4];
        float4 b = *(const float4*)&cur[(size_t)s1 * LAT + lane * 4];
        float4 c = *(const float4*)&cur[(size_t)s2 * LAT + lane * 4];
        float4 d = *(const float4*)&cur[(size_t)s3 * LAT + lane * 4];
        acc.x += (a.x + b.x) + (c.x + d.x);
        acc.y += (a.y + b.y) + (c.y + d.y);
        acc.z += (a.z + b.z) + (c.z + d.z);
        acc.w += (a.w + b.w) + (c.w + d.w);
    }
    for (; j < end; j++) {
        int s0 = __ldg(&csrc[j]);
        float4 a = *(const float4*)&cur[(size_t)s0 * LAT + lane * 4];
        acc.x += a.x; acc.y += a.y; acc.z += a.z; acc.w += a.w;
    }
    *(float4*)&pool[(size_t)node * LAT + lane * 4] = acc;
}

// ---- final: out = leaky(graph accumulator) ----
__global__ void final_k(const float* __restrict__ g, float* __restrict__ out) {
    int i = blockIdx.x * 256 + threadIdx.x;
    if (i < NG * LAT) out[i] = lk(g[i]);
}

// ---------------- launch ----------------
extern "C" void kernel_launch(void* const* d_in, const int* in_sizes, int n_in,
                              void* d_out, int out_size) {
    const float* node_feats = (const float*)d_in[0];
    const float* edge_feats = (const float*)d_in[1];
    const int* edge_src = (const int*)d_in[2];
    const int* edge_dst = (const int*)d_in[3];
    const int* e2n_dst = (const int*)d_in[4];
    const int* graph_ids = (const int*)d_in[5];
    const float* wn = (const float*)d_in[6];
    const float* bn = (const float*)d_in[7];
    const float* we = (const float*)d_in[8];
    const float* be = (const float*)d_in[9];
    const float* wc = (const float*)d_in[10];
    const float* bc = (const float*)d_in[11];
    const float* wo = (const float*)d_in[12];
    const float* bo = (const float*)d_in[13];

    int nn = in_sizes[0] / LAT;
    int ne = in_sizes[1] / EF_DIM;

    float *inmsg, *cur, *pool, *pef, *deg, *graph, *wnT, *wcT, *woT, *weT;
    int *ndeg, *incl, *bsum, *rowptr, *woff, *csrc;
    cudaGetSymbolAddress((void**)&inmsg, g_inmsg);
    cudaGetSymbolAddress((void**)&cur, g_cur);
    cudaGetSymbolAddress((void**)&pool, g_pool);
    cudaGetSymbolAddress((void**)&pef, g_pef);
    cudaGetSymbolAddress((void**)&deg, g_deg);
    cudaGetSymbolAddress((void**)&graph, g_graph);
    cudaGetSymbolAddress((void**)&wnT, g_WnT);
    cudaGetSymbolAddress((void**)&wcT, g_WcT);
    cudaGetSymbolAddress((void**)&woT, g_WoT);
    cudaGetSymbolAddress((void**)&weT, g_WeT);
    cudaGetSymbolAddress((void**)&ndeg, g_ndeg);
    cudaGetSymbolAddress((void**)&incl, g_incl);
    cudaGetSymbolAddress((void**)&bsum, g_bsum);
    cudaGetSymbolAddress((void**)&rowptr, g_rowptr);
    cudaGetSymbolAddress((void**)&woff, g_woff);
    cudaGetSymbolAddress((void**)&csrc, g_csrc);

    const int rowBlocks = (nn + 63) / 64;
    const int edgeBlocks = (ne + 255) / 256;
    const int scanBlocks = (nn + 1023) / 1024;

    // weight transposes (tiny)
    transpose_k<<<64, 256>>>(wn, wnT, LAT, LAT);
    transpose_k<<<64, 256>>>(wc, wcT, LAT, LAT);
    transpose_k<<<64, 256>>>(wo, woT, LAT, LAT);
    transpose_k<<<16, 256>>>(we, weT, LAT, EF_DIM);

    // zero scratch
    zero_k<<<(nn * EF_DIM / 4 + 255) / 256, 256>>>(pef, nn * EF_DIM / 4);
    zero_k<<<(nn / 4 + 255) / 256, 256>>>(deg, nn / 4);
    zero_k<<<(NG * LAT / 4 + 255) / 256, 256>>>(graph, NG * LAT / 4);
    zeroi_k<<<(nn + 255) / 256, 256>>>(ndeg, nn);

    // ---- CSR build for n2n (sorted by dst) ----
    count_deg_k<<<edgeBlocks, 256>>>(edge_dst, ndeg, ne);
    scan1_k<<<scanBlocks, 1024>>>(ndeg, incl, bsum, nn);
    scan2_k<<<1, 32>>>(bsum, scanBlocks);
    scan3_k<<<(nn + 255) / 256, 256>>>(incl, bsum, ndeg, rowptr, woff, nn, ne);
    csr_fill_k<<<edgeBlocks, 256>>>(edge_src, edge_dst, woff, csrc, ne);

    // input message: node linear (writes inmsg)
    gemm128_k<false, false, false><<<rowBlocks, 256>>>(
        node_feats, wnT, bn, nullptr, nullptr, inmsg, nn);

    // pooled edge features + degree
    {
        long total = (long)ne * 8;
        int grid = (int)((total + 255) / 256);
        edge_scatter_k<<<grid, 256>>>(edge_feats, e2n_dst, pef, deg, ne);
    }

    // inmsg += pef @ WeT + deg*be ; cur = leaky(inmsg)
    gemm32_acc_k<<<rowBlocks, 256>>>(pef, weT, be, deg, inmsg, cur, nn);

    // 3 rounds of message passing (gather SpMM, no zeroing, no atomics)
    const int spmmBlocks = (int)(((long)nn * 32 + 255) / 256);
    for (int lv = 0; lv < 3; lv++) {
        spmm_gather_k<<<spmmBlocks, 256>>>(cur, rowptr, csrc, pool, nn);
        gemm128_k<true, true, false><<<rowBlocks, 256>>>(
            pool, wcT, bc, inmsg, nullptr, cur, nn);
    }

    // output linear + leaky + per-graph pooling (atomic)
    gemm128_k<true, false, true><<<rowBlocks, 256>>>(
        cur, woT, bo, nullptr, graph_ids, graph, nn);

    // final leaky to output
    final_k<<<(NG * LAT + 255) / 256, 256>>>(graph, (float*)d_out);
}